// round 3
// baseline (speedup 1.0000x reference)
#include <cuda_runtime.h>

#define WDIM 1024
#define NPIX (WDIM * WDIM)
#define QTR (NPIX / 4)

static __device__ __forceinline__ unsigned long long pack2(float a, float b) {
    unsigned long long r;
    asm("mov.b64 %0, {%1,%2};" : "=l"(r) : "f"(a), "f"(b));
    return r;
}
static __device__ __forceinline__ void fma2(unsigned long long& d, unsigned long long a, unsigned long long b) {
    asm("fma.rn.f32x2 %0, %1, %2, %0;" : "+l"(d) : "l"(a), "l"(b));
}
static __device__ __forceinline__ float2 unpack2(unsigned long long v) {
    float2 r;
    asm("mov.b64 {%0,%1}, %2;" : "=f"(r.x), "=f"(r.y) : "l"(v));
    return r;
}

// softmax(9) + inverse rotation (register selects) + tanh + sigmoid.
// All 13 stores fully coalesced (plane index compile-time, p consecutive per lane).
static __device__ __forceinline__ void epilogue(const float* z, int d, int p,
                                                float* __restrict__ out)
{
    const int rb0 = d & 1;
    const int rb1 = (d >> 1) & 1;

    float mx = z[0];
#pragma unroll
    for (int j = 1; j < 9; j++) mx = fmaxf(mx, z[j]);
    float s[9];
    float sum = 0.0f;
#pragma unroll
    for (int j = 0; j < 9; j++) { s[j] = __expf(z[j] - mx); sum += s[j]; }
    float inv = __fdividef(1.0f, sum);

    const int I0[9] = {0,1,2,3,4,5,6,7,8};
    const int I1[9] = {2,5,8,1,4,7,0,3,6};
    const int I2[9] = {8,7,6,5,4,3,2,1,0};
    const int I3[9] = {6,3,0,7,4,1,8,5,2};
#pragma unroll
    for (int m = 0; m < 9; m++) {
        float v01 = rb0 ? s[I1[m]] : s[I0[m]];
        float v23 = rb0 ? s[I3[m]] : s[I2[m]];
        float v = rb1 ? v23 : v01;
        out[m * NPIX + p] = v * inv;
    }
    out[9 * NPIX + p] = tanhf(z[9]);
#pragma unroll
    for (int m = 0; m < 3; m++)
        out[(10 + m) * NPIX + p] = __fdividef(1.0f, 1.0f + __expf(-z[10 + m]));
}

__global__ void __launch_bounds__(128, 2) energy_cnn_kernel(
    const float* __restrict__ se, const float* __restrict__ te,
    const float* __restrict__ sr, const float* __restrict__ hc,
    const float* __restrict__ rot, const float* __restrict__ w1,
    const float* __restrict__ b1, const float* __restrict__ w2,
    const float* __restrict__ b2, float* __restrict__ out)
{
    // w1s[(c*9+j)*32 + o] = w1[o][c][j]   (w1 global layout: (32,6,3,3))
    __shared__ __align__(16) float w1s[54 * 32];
    // w2s[o*16 + m] = w2[m][o] (m<13), zero-padded rows of 16
    __shared__ __align__(16) float w2s[32 * 16];
    __shared__ __align__(16) unsigned long long b1p[16];
    __shared__ __align__(16) unsigned long long b2p[7];

    const int tid = threadIdx.x;
    for (int i = tid; i < 54 * 32; i += 128) {
        int cj = i >> 5, o = i & 31;
        w1s[i] = w1[o * 54 + cj];
    }
    for (int i = tid; i < 32 * 16; i += 128) {
        int o = i >> 4, m = i & 15;
        w2s[i] = (m < 13) ? w2[m * 32 + o] : 0.0f;
    }
    if (tid < 16) b1p[tid] = pack2(b1[2 * tid], b1[2 * tid + 1]);
    if (tid < 7) {
        float ba = b2[2 * tid];
        float bb = (2 * tid + 1 < 13) ? b2[2 * tid + 1] : 0.0f;
        b2p[tid] = pack2(ba, bb);
    }
    __syncthreads();

    // Four pixels per thread: p, p+N/4, p+N/2, p+3N/4 (coalesced stores,
    // gathers spread across 4 distinct image quarters).
    const int pb = blockIdx.x * 128 + tid;
    const int xb = pb & (WDIM - 1);
    const int yb = pb >> 10;

    const float TP = 6.2831853071795864f;
    int d[4];
    int idx[4][9];
#pragma unroll
    for (int i = 0; i < 4; i++) {
        const int p = pb + i * QTR;
        const int y = yb + i * (WDIM / 4);
        float t = rot[p] / TP * 4.0f;
        int di = ((int)t) & 3;
        d[i] = di;
        const int rb0 = di & 1, rb1 = (di >> 1) & 1;
#pragma unroll
        for (int j = 0; j < 9; j++) {
            const int dy0 = j / 3 - 1, dx0 = j % 3 - 1;
            int ay = rb1 ? -dy0 : dy0;
            int ax = rb1 ? -dx0 : dx0;
            int dy = rb0 ? -ax : ay;
            int dx = rb0 ? ay : ax;
            idx[i][j] = (((y + dy) & (WDIM - 1)) << 10) + ((xb + dx) & (WDIM - 1));
        }
    }

    // ---- layer 1: 54 -> 32, output-pair packed, 4 pixels share every weight load ----
    unsigned long long acc[4][16];
#pragma unroll
    for (int k = 0; k < 16; k++) {
        unsigned long long b = b1p[k];
#pragma unroll
        for (int i = 0; i < 4; i++) acc[i][k] = b;
    }

    const float* chans[6] = { se, te, sr, hc, hc + NPIX, hc + 2 * NPIX };
#pragma unroll
    for (int c = 0; c < 6; c++) {
        const float* __restrict__ ch = chans[c];
#pragma unroll
        for (int j = 0; j < 9; j++) {
            unsigned long long aa[4];
#pragma unroll
            for (int i = 0; i < 4; i++) {
                float a = __ldg(&ch[idx[i][j]]);
                aa[i] = pack2(a, a);
            }
            const ulonglong2* __restrict__ wrow =
                (const ulonglong2*)&w1s[(c * 9 + j) * 32];
#pragma unroll
            for (int k = 0; k < 8; k++) {
                ulonglong2 wv = wrow[k];
#pragma unroll
                for (int i = 0; i < 4; i++) {
                    fma2(acc[i][2 * k],     aa[i], wv.x);
                    fma2(acc[i][2 * k + 1], aa[i], wv.y);
                }
            }
        }
    }

    float h[4][32];
#pragma unroll
    for (int i = 0; i < 4; i++)
#pragma unroll
        for (int k = 0; k < 16; k++) {
            float2 v = unpack2(acc[i][k]);
            h[i][2 * k]     = fmaxf(v.x, 0.0f);
            h[i][2 * k + 1] = fmaxf(v.y, 0.0f);
        }

    // ---- layer 2: 32 -> 13 (7 output pairs, pair 6 = {z12, pad}) ----
    unsigned long long x2[4][7];
#pragma unroll
    for (int m = 0; m < 7; m++) {
        unsigned long long b = b2p[m];
#pragma unroll
        for (int i = 0; i < 4; i++) x2[i][m] = b;
    }
#pragma unroll
    for (int o = 0; o < 32; o++) {
        unsigned long long hh[4];
#pragma unroll
        for (int i = 0; i < 4; i++) hh[i] = pack2(h[i][o], h[i][o]);
        const ulonglong2* __restrict__ wq = (const ulonglong2*)&w2s[o * 16];
        ulonglong2 wv0 = wq[0];
        ulonglong2 wv1 = wq[1];
        ulonglong2 wv2 = wq[2];
        ulonglong2 wv3 = wq[3];
#pragma unroll
        for (int i = 0; i < 4; i++) {
            fma2(x2[i][0], hh[i], wv0.x);
            fma2(x2[i][1], hh[i], wv0.y);
            fma2(x2[i][2], hh[i], wv1.x);
            fma2(x2[i][3], hh[i], wv1.y);
            fma2(x2[i][4], hh[i], wv2.x);
            fma2(x2[i][5], hh[i], wv2.y);
            fma2(x2[i][6], hh[i], wv3.x);
        }
    }

#pragma unroll
    for (int i = 0; i < 4; i++) {
        float z[13];
#pragma unroll
        for (int m = 0; m < 6; m++) {
            float2 v = unpack2(x2[i][m]);
            z[2 * m] = v.x; z[2 * m + 1] = v.y;
        }
        z[12] = unpack2(x2[i][6]).x;
        epilogue(z, d[i], pb + i * QTR, out);
    }
}

extern "C" void kernel_launch(void* const* d_in, const int* in_sizes, int n_in,
                              void* d_out, int out_size)
{
    const float* se  = (const float*)d_in[0];
    const float* te  = (const float*)d_in[1];
    const float* sr  = (const float*)d_in[2];
    const float* hc  = (const float*)d_in[3];
    const float* rot = (const float*)d_in[4];
    const float* w1  = (const float*)d_in[5];
    const float* b1  = (const float*)d_in[6];
    const float* w2  = (const float*)d_in[7];
    const float* b2  = (const float*)d_in[8];
    float* out = (float*)d_out;

    energy_cnn_kernel<<<QTR / 128, 128>>>(se, te, sr, hc, rot, w1, b1, w2, b2, out);
}